// round 1
// baseline (speedup 1.0000x reference)
#include <cuda_runtime.h>
#include <math.h>

#define HID 4096
#define KVD 1024
#define TOK 4096   /* B*S = 2*2048 */
#define SEQ 2048

// ---------------- device scratch (module-load time, not runtime alloc) ----------------
__device__ float g_Wqd[HID * HID];
__device__ float g_Wkd[KVD * HID];
__device__ float g_Wvd[KVD * HID];
__device__ float g_Wod[HID * HID];
__device__ float g_q[TOK * HID];
__device__ float g_k[TOK * KVD];
__device__ float g_v[TOK * KVD];
__device__ float g_att[TOK * HID];

// ---------------- DoRA weight materialization ----------------
// One block per output row: W_eff = W + 2.0 * B@A ; W_d = W_eff * m / (||W_eff|| + 1e-8)
__global__ __launch_bounds__(256) void dora_weights(
    const float* __restrict__ W, const float* __restrict__ A,
    const float* __restrict__ Bm, const float* __restrict__ mvec,
    float* __restrict__ Wd)
{
    const int row = blockIdx.x;
    const int tid = threadIdx.x;
    float b[8];
#pragma unroll
    for (int r = 0; r < 8; r++) b[r] = 2.0f * Bm[row * 8 + r];  // SCALING = 16/8

    const float4* Wrow = (const float4*)(W + (size_t)row * HID);
    float4 w[4];
    float ss = 0.f;
#pragma unroll
    for (int c = 0; c < 4; c++) {
        int col4 = tid + 256 * c;
        float4 wv = Wrow[col4];
#pragma unroll
        for (int r = 0; r < 8; r++) {
            float4 av = ((const float4*)(A + (size_t)r * HID))[col4];
            wv.x += b[r] * av.x; wv.y += b[r] * av.y;
            wv.z += b[r] * av.z; wv.w += b[r] * av.w;
        }
        ss += wv.x * wv.x + wv.y * wv.y + wv.z * wv.z + wv.w * wv.w;
        w[c] = wv;
    }
#pragma unroll
    for (int off = 16; off; off >>= 1)
        ss += __shfl_xor_sync(0xffffffffu, ss, off);

    __shared__ float red[8];
    __shared__ float s_scale;
    if ((tid & 31) == 0) red[tid >> 5] = ss;
    __syncthreads();
    if (tid == 0) {
        float t = 0.f;
#pragma unroll
        for (int i = 0; i < 8; i++) t += red[i];
        s_scale = mvec[row] / (sqrtf(t) + 1e-8f);
    }
    __syncthreads();
    const float sc = s_scale;
    float4* Wdrow = (float4*)(Wd + (size_t)row * HID);
#pragma unroll
    for (int c = 0; c < 4; c++) {
        float4 wv = w[c];
        wv.x *= sc; wv.y *= sc; wv.z *= sc; wv.w *= sc;
        Wdrow[tid + 256 * c] = wv;
    }
}

// ---------------- fp32 tiled GEMM:  C[M,N] = A[M,K] * B[N,K]^T ----------------
// 128x128 block tile, BK=16, 256 threads, 8x8 per-thread microtile.
__global__ __launch_bounds__(256, 2) void gemm_nt(
    const float* __restrict__ A, const float* __restrict__ B,
    float* __restrict__ C, int M, int N, int K)
{
    __shared__ float As[16][132];
    __shared__ float Bs[16][132];
    const int tid = threadIdx.x;
    const int ty = tid >> 4, tx = tid & 15;
    const int row0 = blockIdx.y << 7;
    const int col0 = blockIdx.x << 7;

    const int lr = tid >> 2;          // 0..63 (plus +64 for second half)
    const int lc = (tid & 3) << 2;    // k offset within 16

    const float* Ap = A + (size_t)(row0 + lr) * K + lc;
    const float* Bp = B + (size_t)(col0 + lr) * K + lc;

    float acc[8][8] = {};

    for (int k0 = 0; k0 < K; k0 += 16) {
        float4 a0 = *(const float4*)(Ap + k0);
        float4 a1 = *(const float4*)(Ap + (size_t)64 * K + k0);
        float4 b0 = *(const float4*)(Bp + k0);
        float4 b1 = *(const float4*)(Bp + (size_t)64 * K + k0);
        __syncthreads();
        As[lc + 0][lr] = a0.x; As[lc + 1][lr] = a0.y; As[lc + 2][lr] = a0.z; As[lc + 3][lr] = a0.w;
        As[lc + 0][lr + 64] = a1.x; As[lc + 1][lr + 64] = a1.y; As[lc + 2][lr + 64] = a1.z; As[lc + 3][lr + 64] = a1.w;
        Bs[lc + 0][lr] = b0.x; Bs[lc + 1][lr] = b0.y; Bs[lc + 2][lr] = b0.z; Bs[lc + 3][lr] = b0.w;
        Bs[lc + 0][lr + 64] = b1.x; Bs[lc + 1][lr + 64] = b1.y; Bs[lc + 2][lr + 64] = b1.z; Bs[lc + 3][lr + 64] = b1.w;
        __syncthreads();
#pragma unroll
        for (int kk = 0; kk < 16; kk++) {
            float4 af0 = *(const float4*)&As[kk][ty * 8];
            float4 af1 = *(const float4*)&As[kk][ty * 8 + 4];
            float4 bf0 = *(const float4*)&Bs[kk][tx * 8];
            float4 bf1 = *(const float4*)&Bs[kk][tx * 8 + 4];
            float a[8] = {af0.x, af0.y, af0.z, af0.w, af1.x, af1.y, af1.z, af1.w};
            float bb[8] = {bf0.x, bf0.y, bf0.z, bf0.w, bf1.x, bf1.y, bf1.z, bf1.w};
#pragma unroll
            for (int i = 0; i < 8; i++)
#pragma unroll
                for (int j = 0; j < 8; j++)
                    acc[i][j] += a[i] * bb[j];
        }
    }
#pragma unroll
    for (int i = 0; i < 8; i++) {
        float4 o0 = {acc[i][0], acc[i][1], acc[i][2], acc[i][3]};
        float4 o1 = {acc[i][4], acc[i][5], acc[i][6], acc[i][7]};
        float* Cp = C + (size_t)(row0 + ty * 8 + i) * N + col0 + tx * 8;
        *(float4*)Cp = o0;
        *(float4*)(Cp + 4) = o1;
    }
}

// ---------------- causal flash attention (fp32) ----------------
// Grid: (qtile=32, head=32, batch=2). Block 256 (16x16 thread grid).
// Tiles: 64 queries x 64 keys x 128 dims. Online softmax; GQA via kvh = h/4.
// Thread (ty,tx): score rows {ty+16i}, score cols {tx+16j}, out dims {tx+16jj}.
#define QSTR 132
#define PSTR 68
#define FLASH_SMEM ((3 * 64 * QSTR + 64 * PSTR) * 4)

__global__ __launch_bounds__(256) void flash_attn(
    const float* __restrict__ q, const float* __restrict__ k,
    const float* __restrict__ v, float* __restrict__ o)
{
    extern __shared__ float sm[];
    float* Qs = sm;                     // [64][132]
    float* Ks = sm + 64 * QSTR;        // [64][132]
    float* Vs = sm + 2 * 64 * QSTR;    // [64][132]
    float* Ps = sm + 3 * 64 * QSTR;    // [64][68]

    const int tid = threadIdx.x;
    const int ty = tid >> 4, tx = tid & 15;
    const int qt = blockIdx.x, h = blockIdx.y, b = blockIdx.z;
    const int kvh = h >> 2;
    const float rsc = 0.08838834764831845f;  // 1/sqrt(128)

    // load Q tile, pre-scaled
    const size_t qbase = ((size_t)(b * SEQ + qt * 64)) * HID + h * 128;
    for (int idx = tid; idx < 64 * 32; idx += 256) {
        int r = idx >> 5, c4 = (idx & 31) * 4;
        float4 val = *(const float4*)(q + qbase + (size_t)r * HID + c4);
        val.x *= rsc; val.y *= rsc; val.z *= rsc; val.w *= rsc;
        *(float4*)(Qs + r * QSTR + c4) = val;
    }

    float m_i[4], l_i[4], O[4][8];
#pragma unroll
    for (int i = 0; i < 4; i++) {
        m_i[i] = -1e30f; l_i[i] = 0.f;
#pragma unroll
        for (int jj = 0; jj < 8; jj++) O[i][jj] = 0.f;
    }

    for (int kt = 0; kt <= qt; kt++) {
        __syncthreads();   // prior PV reads of Ks/Vs/Ps done
        const size_t kbase = ((size_t)(b * SEQ + kt * 64)) * KVD + kvh * 128;
        for (int idx = tid; idx < 64 * 32; idx += 256) {
            int r = idx >> 5, c4 = (idx & 31) * 4;
            *(float4*)(Ks + r * QSTR + c4) = *(const float4*)(k + kbase + (size_t)r * KVD + c4);
            *(float4*)(Vs + r * QSTR + c4) = *(const float4*)(v + kbase + (size_t)r * KVD + c4);
        }
        __syncthreads();

        // scores: s[i][j] = Qrow(ty+16i) . Krow(tx+16j)
        float s[4][4] = {};
#pragma unroll 4
        for (int kk = 0; kk < 128; kk += 4) {
            float4 qf[4], kf[4];
#pragma unroll
            for (int i = 0; i < 4; i++) qf[i] = *(const float4*)(Qs + (ty + 16 * i) * QSTR + kk);
#pragma unroll
            for (int j = 0; j < 4; j++) kf[j] = *(const float4*)(Ks + (tx + 16 * j) * QSTR + kk);
#pragma unroll
            for (int i = 0; i < 4; i++)
#pragma unroll
                for (int j = 0; j < 4; j++)
                    s[i][j] += qf[i].x * kf[j].x + qf[i].y * kf[j].y +
                               qf[i].z * kf[j].z + qf[i].w * kf[j].w;
        }
        if (kt == qt) {
#pragma unroll
            for (int i = 0; i < 4; i++)
#pragma unroll
                for (int j = 0; j < 4; j++)
                    if (tx + 16 * j > ty + 16 * i) s[i][j] = -1e30f;
        }

        // online softmax per row (16 lanes share a row; xor-reduce width 16)
#pragma unroll
        for (int i = 0; i < 4; i++) {
            float mx = fmaxf(fmaxf(s[i][0], s[i][1]), fmaxf(s[i][2], s[i][3]));
#pragma unroll
            for (int off = 8; off; off >>= 1)
                mx = fmaxf(mx, __shfl_xor_sync(0xffffffffu, mx, off, 16));
            float mnew = fmaxf(m_i[i], mx);
            float corr = __expf(m_i[i] - mnew);
            m_i[i] = mnew;
            float rs = 0.f;
#pragma unroll
            for (int j = 0; j < 4; j++) {
                float p = __expf(s[i][j] - mnew);
                s[i][j] = p;
                rs += p;
            }
#pragma unroll
            for (int off = 8; off; off >>= 1)
                rs += __shfl_xor_sync(0xffffffffu, rs, off, 16);
            l_i[i] = l_i[i] * corr + rs;
#pragma unroll
            for (int jj = 0; jj < 8; jj++) O[i][jj] *= corr;
#pragma unroll
            for (int j = 0; j < 4; j++)
                Ps[(ty + 16 * i) * PSTR + tx + 16 * j] = s[i][j];
        }
        __syncthreads();

        // PV: O[i][jj] += sum_j P[row_i][j] * V[j][dim_jj]
#pragma unroll 4
        for (int j = 0; j < 64; j++) {
            float pf[4];
#pragma unroll
            for (int i = 0; i < 4; i++) pf[i] = Ps[(ty + 16 * i) * PSTR + j];
            float vf[8];
#pragma unroll
            for (int jj = 0; jj < 8; jj++) vf[jj] = Vs[j * QSTR + tx + 16 * jj];
#pragma unroll
            for (int i = 0; i < 4; i++)
#pragma unroll
                for (int jj = 0; jj < 8; jj++)
                    O[i][jj] += pf[i] * vf[jj];
        }
    }

    // epilogue
    const size_t obase = ((size_t)(b * SEQ + qt * 64)) * HID + h * 128;
#pragma unroll
    for (int i = 0; i < 4; i++) {
        float inv = 1.f / l_i[i];
#pragma unroll
        for (int jj = 0; jj < 8; jj++)
            o[obase + (size_t)(ty + 16 * i) * HID + tx + 16 * jj] = O[i][jj] * inv;
    }
}

// ---------------- launch ----------------
extern "C" void kernel_launch(void* const* d_in, const int* in_sizes, int n_in,
                              void* d_out, int out_size)
{
    const float* x  = (const float*)d_in[0];
    /* d_in[1] = attention_mask: exactly causal -1e9; handled analytically */
    const float* Wq = (const float*)d_in[2];
    const float* Aq = (const float*)d_in[3];
    const float* Bq = (const float*)d_in[4];
    const float* mq = (const float*)d_in[5];
    const float* Wk = (const float*)d_in[6];
    const float* Ak = (const float*)d_in[7];
    const float* Bk = (const float*)d_in[8];
    const float* mk = (const float*)d_in[9];
    const float* Wv = (const float*)d_in[10];
    const float* Av = (const float*)d_in[11];
    const float* Bv = (const float*)d_in[12];
    const float* mv = (const float*)d_in[13];
    const float* Wo = (const float*)d_in[14];
    const float* Ao = (const float*)d_in[15];
    const float* Bo = (const float*)d_in[16];
    const float* mo = (const float*)d_in[17];

    float *Wqd, *Wkd, *Wvd, *Wod, *qb, *kb, *vb, *ab;
    cudaGetSymbolAddress((void**)&Wqd, g_Wqd);
    cudaGetSymbolAddress((void**)&Wkd, g_Wkd);
    cudaGetSymbolAddress((void**)&Wvd, g_Wvd);
    cudaGetSymbolAddress((void**)&Wod, g_Wod);
    cudaGetSymbolAddress((void**)&qb, g_q);
    cudaGetSymbolAddress((void**)&kb, g_k);
    cudaGetSymbolAddress((void**)&vb, g_v);
    cudaGetSymbolAddress((void**)&ab, g_att);

    cudaFuncSetAttribute(flash_attn, cudaFuncAttributeMaxDynamicSharedMemorySize, FLASH_SMEM);

    // 1) DoRA effective weights
    dora_weights<<<HID, 256>>>(Wq, Aq, Bq, mq, Wqd);
    dora_weights<<<KVD, 256>>>(Wk, Ak, Bk, mk, Wkd);
    dora_weights<<<KVD, 256>>>(Wv, Av, Bv, mv, Wvd);
    dora_weights<<<HID, 256>>>(Wo, Ao, Bo, mo, Wod);

    // 2) q/k/v projections
    gemm_nt<<<dim3(HID / 128, TOK / 128), 256>>>(x, Wqd, qb, TOK, HID, HID);
    gemm_nt<<<dim3(KVD / 128, TOK / 128), 256>>>(x, Wkd, kb, TOK, KVD, HID);
    gemm_nt<<<dim3(KVD / 128, TOK / 128), 256>>>(x, Wvd, vb, TOK, KVD, HID);

    // 3) causal attention
    flash_attn<<<dim3(SEQ / 64, 32, 2), 256, FLASH_SMEM>>>(qb, kb, vb, ab);

    // 4) output projection -> d_out
    gemm_nt<<<dim3(HID / 128, TOK / 128), 256>>>(ab, Wod, (float*)d_out, TOK, HID, HID);
}

// round 3
// speedup vs baseline: 1.7204x; 1.7204x over previous
#include <cuda_runtime.h>
#include <cuda_bf16.h>
#include <cstdint>
#include <math.h>

#define HID 4096
#define KVD 1024
#define TOK 4096   /* B*S */
#define SEQ 2048

// ---------------- device scratch ----------------
__device__ __nv_bfloat16 g_xh[TOK * HID];
__device__ __nv_bfloat16 g_xl[TOK * HID];
__device__ __nv_bfloat16 g_Wqh[HID * HID];
__device__ __nv_bfloat16 g_Wql[HID * HID];
__device__ __nv_bfloat16 g_Wkh[KVD * HID];
__device__ __nv_bfloat16 g_Wkl[KVD * HID];
__device__ __nv_bfloat16 g_Wvh[KVD * HID];
__device__ __nv_bfloat16 g_Wvl[KVD * HID];
__device__ __nv_bfloat16 g_Woh[HID * HID];
__device__ __nv_bfloat16 g_Wol[HID * HID];
__device__ float g_q[TOK * HID];
__device__ float g_k[TOK * KVD];
__device__ float g_v[TOK * KVD];
__device__ float g_att[TOK * HID];
__device__ __nv_bfloat16 g_ath[TOK * HID];
__device__ __nv_bfloat16 g_atl[TOK * HID];

// ---------------- helpers ----------------
__device__ __forceinline__ uint32_t smem_u32(const void* p) {
    uint32_t a;
    asm("{ .reg .u64 t; cvta.to.shared.u64 t, %1; cvt.u32.u64 %0, t; }" : "=r"(a) : "l"(p));
    return a;
}
__device__ __forceinline__ void cp16(uint32_t dst, const void* src) {
    asm volatile("cp.async.cg.shared.global [%0], [%1], 16;\n" :: "r"(dst), "l"(src) : "memory");
}
#define CP_COMMIT() asm volatile("cp.async.commit_group;\n" ::: "memory")

#define LDSM4(r, a) \
    asm volatile("ldmatrix.sync.aligned.m8n8.x4.shared.b16 {%0,%1,%2,%3}, [%4];" \
                 : "=r"((r)[0]), "=r"((r)[1]), "=r"((r)[2]), "=r"((r)[3]) : "r"(a))

#define MMA16816(d, a, b0, b1) \
    asm volatile("mma.sync.aligned.m16n8k16.row.col.f32.bf16.bf16.f32 " \
                 "{%0,%1,%2,%3}, {%4,%5,%6,%7}, {%8,%9}, {%0,%1,%2,%3};" \
                 : "+f"((d)[0]), "+f"((d)[1]), "+f"((d)[2]), "+f"((d)[3]) \
                 : "r"((a)[0]), "r"((a)[1]), "r"((a)[2]), "r"((a)[3]), "r"(b0), "r"(b1))

// ---------------- DoRA weight materialization -> bf16 hi/lo ----------------
__global__ __launch_bounds__(256) void dora_weights(
    const float* __restrict__ W, const float* __restrict__ A,
    const float* __restrict__ Bm, const float* __restrict__ mvec,
    __nv_bfloat16* __restrict__ Whi, __nv_bfloat16* __restrict__ Wlo)
{
    const int row = blockIdx.x;
    const int tid = threadIdx.x;
    float b[8];
#pragma unroll
    for (int r = 0; r < 8; r++) b[r] = 2.0f * Bm[row * 8 + r];

    const float4* Wrow = (const float4*)(W + (size_t)row * HID);
    float4 w[4];
    float ss = 0.f;
#pragma unroll
    for (int c = 0; c < 4; c++) {
        int col4 = tid + 256 * c;
        float4 wv = Wrow[col4];
#pragma unroll
        for (int r = 0; r < 8; r++) {
            float4 av = ((const float4*)(A + (size_t)r * HID))[col4];
            wv.x += b[r] * av.x; wv.y += b[r] * av.y;
            wv.z += b[r] * av.z; wv.w += b[r] * av.w;
        }
        ss += wv.x * wv.x + wv.y * wv.y + wv.z * wv.z + wv.w * wv.w;
        w[c] = wv;
    }
#pragma unroll
    for (int off = 16; off; off >>= 1)
        ss += __shfl_xor_sync(0xffffffffu, ss, off);

    __shared__ float red[8];
    __shared__ float s_scale;
    if ((tid & 31) == 0) red[tid >> 5] = ss;
    __syncthreads();
    if (tid == 0) {
        float t = 0.f;
#pragma unroll
        for (int i = 0; i < 8; i++) t += red[i];
        s_scale = mvec[row] / (sqrtf(t) + 1e-8f);
    }
    __syncthreads();
    const float sc = s_scale;
#pragma unroll
    for (int c = 0; c < 4; c++) {
        float vv[4] = {w[c].x * sc, w[c].y * sc, w[c].z * sc, w[c].w * sc};
        size_t base = (size_t)row * HID + (tid + 256 * c) * 4;
#pragma unroll
        for (int e = 0; e < 4; e++) {
            __nv_bfloat16 h = __float2bfloat16(vv[e]);
            Whi[base + e] = h;
            Wlo[base + e] = __float2bfloat16(vv[e] - __bfloat162float(h));
        }
    }
}

// ---------------- fp32 -> bf16 hi/lo split ----------------
__global__ __launch_bounds__(256) void split_bf16(
    const float* __restrict__ in, __nv_bfloat16* __restrict__ hi,
    __nv_bfloat16* __restrict__ lo, int n4)
{
    int i = blockIdx.x * 256 + threadIdx.x;
    if (i >= n4) return;
    float4 v = ((const float4*)in)[i];
    float vv[4] = {v.x, v.y, v.z, v.w};
    size_t base = (size_t)i * 4;
#pragma unroll
    for (int e = 0; e < 4; e++) {
        __nv_bfloat16 h = __float2bfloat16(vv[e]);
        hi[base + e] = h;
        lo[base + e] = __float2bfloat16(vv[e] - __bfloat162float(h));
    }
}

// ---------------- HMMA GEMM: C[M,N] = A[M,K]*B[N,K]^T, bf16 3-term split ----
// 128x128 CTA tile, 256 threads (4x2 warps, warp tile 32x64), K chunk 32,
// cp.async double buffer. K = 4096 fixed. Smem rows padded to 80B for
// conflict-free ldmatrix.
#define STRIDE_B 80                      /* bytes per 32-elem bf16 row */
#define TILE_B   (128 * STRIDE_B)        /* 10240 */
#define STAGE_B  (4 * TILE_B)            /* 40960 */
#define GEMM_SMEM (2 * STAGE_B)          /* 81920 */

__global__ __launch_bounds__(256, 1) void gemm_hmma(
    const __nv_bfloat16* __restrict__ Ah, const __nv_bfloat16* __restrict__ Al,
    const __nv_bfloat16* __restrict__ Bh, const __nv_bfloat16* __restrict__ Bl,
    float* __restrict__ C, int N)
{
    extern __shared__ char dsm[];
    const uint32_t sb = smem_u32(dsm);
    const int tid = threadIdx.x, lane = tid & 31, wid = tid >> 5;
    const int wm = wid & 3, wn = wid >> 2;
    const int row0 = blockIdx.y << 7, col0 = blockIdx.x << 7;
    const int K = 4096;

    const __nv_bfloat16* g0 = Ah + (size_t)row0 * K;
    const __nv_bfloat16* g1 = Al + (size_t)row0 * K;
    const __nv_bfloat16* g2 = Bh + (size_t)col0 * K;
    const __nv_bfloat16* g3 = Bl + (size_t)col0 * K;

    const int ldr = tid >> 2;            // row 0..63 (and +64)
    const int ldc = (tid & 3) * 16;      // byte col within 64B row

    // ldmatrix lane address components
    const uint32_t a_off = (uint32_t)(wm * 32 + (lane & 15)) * STRIDE_B + ((lane >> 4) * 16);
    const uint32_t b_off = (uint32_t)(wn * 64 + (((lane >> 4) << 3) + (lane & 7))) * STRIDE_B
                           + (((lane >> 3) & 1) * 16);

    float acc[2][8][4] = {};

#define LOAD_STAGE(buf, k0) do { \
    uint32_t s0_ = sb + (buf) * STAGE_B; \
    const __nv_bfloat16* gg_[4] = {g0 + (k0), g1 + (k0), g2 + (k0), g3 + (k0)}; \
    _Pragma("unroll") \
    for (int t_ = 0; t_ < 4; t_++) { \
        uint32_t st_ = s0_ + t_ * TILE_B; \
        _Pragma("unroll") \
        for (int p_ = 0; p_ < 2; p_++) { \
            int r_ = ldr + p_ * 64; \
            cp16(st_ + (uint32_t)r_ * STRIDE_B + ldc, \
                 (const char*)(gg_[t_] + (size_t)r_ * K) + ldc); \
        } \
    } \
    CP_COMMIT(); \
} while (0)

    LOAD_STAGE(0, 0);
    for (int ch = 0; ch < 128; ch++) {
        if (ch + 1 < 128) {
            LOAD_STAGE((ch + 1) & 1, (ch + 1) * 32);
            asm volatile("cp.async.wait_group 1;\n" ::: "memory");
        } else {
            asm volatile("cp.async.wait_group 0;\n" ::: "memory");
        }
        __syncthreads();
        const uint32_t s0 = sb + (ch & 1) * STAGE_B;
        const uint32_t sAh = s0, sAl = s0 + TILE_B;
        const uint32_t sBh = s0 + 2 * TILE_B, sBl = s0 + 3 * TILE_B;
#pragma unroll
        for (int k16 = 0; k16 < 2; k16++) {
            const uint32_t kadd = k16 * 32;   // 16 elems * 2B
            uint32_t ah[2][4], al[2][4], bb[4][4];
            LDSM4(ah[0], sAh + a_off + kadd);
            LDSM4(ah[1], sAh + a_off + 16 * STRIDE_B + kadd);
            LDSM4(al[0], sAl + a_off + kadd);
            LDSM4(al[1], sAl + a_off + 16 * STRIDE_B + kadd);
#pragma unroll
            for (int j = 0; j < 4; j++) LDSM4(bb[j], sBh + b_off + j * 16 * STRIDE_B + kadd);
#pragma unroll
            for (int i = 0; i < 2; i++)
#pragma unroll
                for (int f = 0; f < 8; f++)
                    MMA16816(acc[i][f], ah[i], bb[f >> 1][(f & 1) * 2], bb[f >> 1][(f & 1) * 2 + 1]);
#pragma unroll
            for (int i = 0; i < 2; i++)
#pragma unroll
                for (int f = 0; f < 8; f++)
                    MMA16816(acc[i][f], al[i], bb[f >> 1][(f & 1) * 2], bb[f >> 1][(f & 1) * 2 + 1]);
#pragma unroll
            for (int j = 0; j < 4; j++) LDSM4(bb[j], sBl + b_off + j * 16 * STRIDE_B + kadd);
#pragma unroll
            for (int i = 0; i < 2; i++)
#pragma unroll
                for (int f = 0; f < 8; f++)
                    MMA16816(acc[i][f], ah[i], bb[f >> 1][(f & 1) * 2], bb[f >> 1][(f & 1) * 2 + 1]);
        }
        __syncthreads();
    }
#undef LOAD_STAGE

    // epilogue
#pragma unroll
    for (int i = 0; i < 2; i++) {
        const int mrow = row0 + wm * 32 + i * 16 + (lane >> 2);
#pragma unroll
        for (int f = 0; f < 8; f++) {
            const int col = col0 + wn * 64 + f * 8 + (lane & 3) * 2;
            float2 lo2 = {acc[i][f][0], acc[i][f][1]};
            float2 hi2 = {acc[i][f][2], acc[i][f][3]};
            *(float2*)&C[(size_t)mrow * N + col] = lo2;
            *(float2*)&C[(size_t)(mrow + 8) * N + col] = hi2;
        }
    }
}

// ---------------- causal flash attention (fp32) ----------------
#define QSTR 132
#define PSTR 68
#define FLASH_SMEM ((3 * 64 * QSTR + 64 * PSTR) * 4)

__global__ __launch_bounds__(256) void flash_attn(
    const float* __restrict__ q, const float* __restrict__ k,
    const float* __restrict__ v, float* __restrict__ o)
{
    extern __shared__ float sm[];
    float* Qs = sm;
    float* Ks = sm + 64 * QSTR;
    float* Vs = sm + 2 * 64 * QSTR;
    float* Ps = sm + 3 * 64 * QSTR;

    const int tid = threadIdx.x;
    const int ty = tid >> 4, tx = tid & 15;
    const int qt = blockIdx.x, h = blockIdx.y, b = blockIdx.z;
    const int kvh = h >> 2;
    const float rsc = 0.08838834764831845f;

    const size_t qbase = ((size_t)(b * SEQ + qt * 64)) * HID + h * 128;
    for (int idx = tid; idx < 64 * 32; idx += 256) {
        int r = idx >> 5, c4 = (idx & 31) * 4;
        float4 val = *(const float4*)(q + qbase + (size_t)r * HID + c4);
        val.x *= rsc; val.y *= rsc; val.z *= rsc; val.w *= rsc;
        *(float4*)(Qs + r * QSTR + c4) = val;
    }

    float m_i[4], l_i[4], O[4][8];
#pragma unroll
    for (int i = 0; i < 4; i++) {
        m_i[i] = -1e30f; l_i[i] = 0.f;
#pragma unroll
        for (int jj = 0; jj < 8; jj++) O[i][jj] = 0.f;
    }

    for (int kt = 0; kt <= qt; kt++) {
        __syncthreads();
        const size_t kbase = ((size_t)(b * SEQ + kt * 64)) * KVD + kvh * 128;
        for (int idx = tid; idx < 64 * 32; idx += 256) {
            int r = idx >> 5, c4 = (idx & 31) * 4;
            *(float4*)(Ks + r * QSTR + c4) = *(const float4*)(k + kbase + (size_t)r * KVD + c4);
            *(float4*)(Vs + r * QSTR + c4) = *(const float4*)(v + kbase + (size_t)r * KVD + c4);
        }
        __syncthreads();

        float s[4][4] = {};
#pragma unroll 4
        for (int kk = 0; kk < 128; kk += 4) {
            float4 qf[4], kf[4];
#pragma unroll
            for (int i = 0; i < 4; i++) qf[i] = *(const float4*)(Qs + (ty + 16 * i) * QSTR + kk);
#pragma unroll
            for (int j = 0; j < 4; j++) kf[j] = *(const float4*)(Ks + (tx + 16 * j) * QSTR + kk);
#pragma unroll
            for (int i = 0; i < 4; i++)
#pragma unroll
                for (int j = 0; j < 4; j++)
                    s[i][j] += qf[i].x * kf[j].x + qf[i].y * kf[j].y +
                               qf[i].z * kf[j].z + qf[i].w * kf[j].w;
        }
        if (kt == qt) {
#pragma unroll
            for (int i = 0; i < 4; i++)
#pragma unroll
                for (int j = 0; j < 4; j++)
                    if (tx + 16 * j > ty + 16 * i) s[i][j] = -1e30f;
        }

#pragma unroll
        for (int i = 0; i < 4; i++) {
            float mx = fmaxf(fmaxf(s[i][0], s[i][1]), fmaxf(s[i][2], s[i][3]));
#pragma unroll
            for (int off = 8; off; off >>= 1)
                mx = fmaxf(mx, __shfl_xor_sync(0xffffffffu, mx, off, 16));
            float mnew = fmaxf(m_i[i], mx);
            float corr = __expf(m_i[i] - mnew);
            m_i[i] = mnew;
            float rs = 0.f;
#pragma unroll
            for (int j = 0; j < 4; j++) {
                float p = __expf(s[i][j] - mnew);
                s[i][j] = p;
                rs += p;
            }
#pragma unroll
            for (int off = 8; off; off >>= 1)
                rs += __shfl_xor_sync(0xffffffffu, rs, off, 16);
            l_i[i] = l_i[i] * corr + rs;
#pragma unroll
            for (int jj = 0; jj < 8; jj++) O[i][jj] *= corr;
#pragma unroll
            for (int j = 0; j < 4; j++)
                Ps[(ty + 16 * i) * PSTR + tx + 16 * j] = s[i][j];
        }
        __syncthreads();

#pragma unroll 4
        for (int j = 0; j < 64; j++) {
            float pf[4];
#pragma unroll
            for (int i = 0; i < 4; i++) pf[i] = Ps[(ty + 16 * i) * PSTR + j];
            float vf[8];
#pragma unroll
            for (int jj = 0; jj < 8; jj++) vf[jj] = Vs[j * QSTR + tx + 16 * jj];
#pragma unroll
            for (int i = 0; i < 4; i++)
#pragma unroll
                for (int jj = 0; jj < 8; jj++)
                    O[i][jj] += pf[i] * vf[jj];
        }
    }

    const size_t obase = ((size_t)(b * SEQ + qt * 64)) * HID + h * 128;
#pragma unroll
    for (int i = 0; i < 4; i++) {
        float inv = 1.f / l_i[i];
#pragma unroll
        for (int jj = 0; jj < 8; jj++)
            o[obase + (size_t)(ty + 16 * i) * HID + tx + 16 * jj] = O[i][jj] * inv;
    }
}

// ---------------- launch ----------------
extern "C" void kernel_launch(void* const* d_in, const int* in_sizes, int n_in,
                              void* d_out, int out_size)
{
    const float* x  = (const float*)d_in[0];
    const float* Wq = (const float*)d_in[2];
    const float* Aq = (const float*)d_in[3];
    const float* Bq = (const float*)d_in[4];
    const float* mq = (const float*)d_in[5];
    const float* Wk = (const float*)d_in[6];
    const float* Ak = (const float*)d_in[7];
    const float* Bk = (const float*)d_in[8];
    const float* mk = (const float*)d_in[9];
    const float* Wv = (const float*)d_in[10];
    const float* Av = (const float*)d_in[11];
    const float* Bv = (const float*)d_in[12];
    const float* mv = (const float*)d_in[13];
    const float* Wo = (const float*)d_in[14];
    const float* Ao = (const float*)d_in[15];
    const float* Bo = (const float*)d_in[16];
    const float* mo = (const float*)d_in[17];

    __nv_bfloat16 *xh, *xl, *Wqh, *Wql, *Wkh, *Wkl, *Wvh, *Wvl, *Woh, *Wol, *ath, *atl;
    float *qb, *kb, *vb, *ab;
    cudaGetSymbolAddress((void**)&xh, g_xh);   cudaGetSymbolAddress((void**)&xl, g_xl);
    cudaGetSymbolAddress((void**)&Wqh, g_Wqh); cudaGetSymbolAddress((void**)&Wql, g_Wql);
    cudaGetSymbolAddress((void**)&Wkh, g_Wkh); cudaGetSymbolAddress((void**)&Wkl, g_Wkl);
    cudaGetSymbolAddress((void**)&Wvh, g_Wvh); cudaGetSymbolAddress((void**)&Wvl, g_Wvl);
    cudaGetSymbolAddress((void**)&Woh, g_Woh); cudaGetSymbolAddress((void**)&Wol, g_Wol);
    cudaGetSymbolAddress((void**)&ath, g_ath); cudaGetSymbolAddress((void**)&atl, g_atl);
    cudaGetSymbolAddress((void**)&qb, g_q);    cudaGetSymbolAddress((void**)&kb, g_k);
    cudaGetSymbolAddress((void**)&vb, g_v);    cudaGetSymbolAddress((void**)&ab, g_att);

    cudaFuncSetAttribute(flash_attn, cudaFuncAttributeMaxDynamicSharedMemorySize, FLASH_SMEM);
    cudaFuncSetAttribute(gemm_hmma, cudaFuncAttributeMaxDynamicSharedMemorySize, GEMM_SMEM);

    // 1) DoRA effective weights (bf16 hi/lo)
    dora_weights<<<HID, 256>>>(Wq, Aq, Bq, mq, Wqh, Wql);
    dora_weights<<<KVD, 256>>>(Wk, Ak, Bk, mk, Wkh, Wkl);
    dora_weights<<<KVD, 256>>>(Wv, Av, Bv, mv, Wvh, Wvl);
    dora_weights<<<HID, 256>>>(Wo, Ao, Bo, mo, Woh, Wol);

    // 2) split x
    split_bf16<<<(TOK * HID / 4 + 255) / 256, 256>>>(x, xh, xl, TOK * HID / 4);

    // 3) q/k/v projections (HMMA tensor cores)
    gemm_hmma<<<dim3(HID / 128, TOK / 128), 256, GEMM_SMEM>>>(xh, xl, Wqh, Wql, qb, HID);
    gemm_hmma<<<dim3(KVD / 128, TOK / 128), 256, GEMM_SMEM>>>(xh, xl, Wkh, Wkl, kb, KVD);
    gemm_hmma<<<dim3(KVD / 128, TOK / 128), 256, GEMM_SMEM>>>(xh, xl, Wvh, Wvl, vb, KVD);

    // 4) causal attention
    flash_attn<<<dim3(SEQ / 64, 32, 2), 256, FLASH_SMEM>>>(qb, kb, vb, ab);

    // 5) split attention output, output projection -> d_out
    split_bf16<<<(TOK * HID / 4 + 255) / 256, 256>>>(ab, ath, atl, TOK * HID / 4);
    gemm_hmma<<<dim3(HID / 128, TOK / 128), 256, GEMM_SMEM>>>(ath, atl, Woh, Wol, (float*)d_out, HID);
}

// round 4
// speedup vs baseline: 2.4090x; 1.4003x over previous
#include <cuda_runtime.h>
#include <cuda_bf16.h>
#include <cstdint>
#include <math.h>

#define HID 4096
#define KVD 1024
#define TOK 4096   /* B*S */
#define SEQ 2048

// ---------------- device scratch ----------------
__device__ __nv_bfloat16 g_xh[TOK * HID];
__device__ __nv_bfloat16 g_xl[TOK * HID];
__device__ __nv_bfloat16 g_Wqh[HID * HID];
__device__ __nv_bfloat16 g_Wql[HID * HID];
__device__ __nv_bfloat16 g_Wkh[KVD * HID];
__device__ __nv_bfloat16 g_Wkl[KVD * HID];
__device__ __nv_bfloat16 g_Wvh[KVD * HID];
__device__ __nv_bfloat16 g_Wvl[KVD * HID];
__device__ __nv_bfloat16 g_Woh[HID * HID];
__device__ __nv_bfloat16 g_Wol[HID * HID];
__device__ __nv_bfloat16 g_qh[TOK * HID];
__device__ __nv_bfloat16 g_ql[TOK * HID];
__device__ __nv_bfloat16 g_kh[TOK * KVD];
__device__ __nv_bfloat16 g_kl[TOK * KVD];
__device__ __nv_bfloat16 g_vh[TOK * KVD];
__device__ __nv_bfloat16 g_vl[TOK * KVD];
__device__ __nv_bfloat16 g_ath[TOK * HID];
__device__ __nv_bfloat16 g_atl[TOK * HID];

// ---------------- helpers ----------------
__device__ __forceinline__ uint32_t smem_u32(const void* p) {
    uint32_t a;
    asm("{ .reg .u64 t; cvta.to.shared.u64 t, %1; cvt.u32.u64 %0, t; }" : "=r"(a) : "l"(p));
    return a;
}
__device__ __forceinline__ void cp16(uint32_t dst, const void* src) {
    asm volatile("cp.async.cg.shared.global [%0], [%1], 16;\n" :: "r"(dst), "l"(src) : "memory");
}
#define CP_COMMIT() asm volatile("cp.async.commit_group;\n" ::: "memory")

#define LDSM4(r, a) \
    asm volatile("ldmatrix.sync.aligned.m8n8.x4.shared.b16 {%0,%1,%2,%3}, [%4];" \
                 : "=r"((r)[0]), "=r"((r)[1]), "=r"((r)[2]), "=r"((r)[3]) : "r"(a))
#define LDSM4T(r, a) \
    asm volatile("ldmatrix.sync.aligned.m8n8.x4.trans.shared.b16 {%0,%1,%2,%3}, [%4];" \
                 : "=r"((r)[0]), "=r"((r)[1]), "=r"((r)[2]), "=r"((r)[3]) : "r"(a))

#define MMA16816(d, a, b0, b1) \
    asm volatile("mma.sync.aligned.m16n8k16.row.col.f32.bf16.bf16.f32 " \
                 "{%0,%1,%2,%3}, {%4,%5,%6,%7}, {%8,%9}, {%0,%1,%2,%3};" \
                 : "+f"((d)[0]), "+f"((d)[1]), "+f"((d)[2]), "+f"((d)[3]) \
                 : "r"((a)[0]), "r"((a)[1]), "r"((a)[2]), "r"((a)[3]), "r"(b0), "r"(b1))

__device__ __forceinline__ uint32_t pack_bf16x2(float hi_, float lo_) {
    uint32_t r;
    asm("cvt.rn.bf16x2.f32 %0, %1, %2;" : "=r"(r) : "f"(hi_), "f"(lo_));
    return r;
}
__device__ __forceinline__ float2 unpack_bf16x2(uint32_t u) {
    float2 r;
    r.x = __uint_as_float(u << 16);
    r.y = __uint_as_float(u & 0xffff0000u);
    return r;
}
// fast exp2 on FMA pipe (no MUFU). x <= 0 expected; rel err ~2.4e-6.
__device__ __forceinline__ float exp2p(float x) {
    x = fmaxf(x, -120.f);
    int e = __float2int_rn(x);
    float f = x - (float)e;
    float p = 1.3333558e-3f;
    p = fmaf(p, f, 9.6181291e-3f);
    p = fmaf(p, f, 5.5504109e-2f);
    p = fmaf(p, f, 2.4022651e-1f);
    p = fmaf(p, f, 6.9314718e-1f);
    p = fmaf(p, f, 1.0f);
    return p * __int_as_float((uint32_t)(e + 127) << 23);
}

// ---------------- DoRA weight materialization -> bf16 hi/lo ----------------
__global__ __launch_bounds__(256) void dora_weights(
    const float* __restrict__ W, const float* __restrict__ A,
    const float* __restrict__ Bm, const float* __restrict__ mvec,
    __nv_bfloat16* __restrict__ Whi, __nv_bfloat16* __restrict__ Wlo)
{
    const int row = blockIdx.x;
    const int tid = threadIdx.x;
    float b[8];
#pragma unroll
    for (int r = 0; r < 8; r++) b[r] = 2.0f * Bm[row * 8 + r];

    const float4* Wrow = (const float4*)(W + (size_t)row * HID);
    float4 w[4];
    float ss = 0.f;
#pragma unroll
    for (int c = 0; c < 4; c++) {
        int col4 = tid + 256 * c;
        float4 wv = Wrow[col4];
#pragma unroll
        for (int r = 0; r < 8; r++) {
            float4 av = ((const float4*)(A + (size_t)r * HID))[col4];
            wv.x += b[r] * av.x; wv.y += b[r] * av.y;
            wv.z += b[r] * av.z; wv.w += b[r] * av.w;
        }
        ss += wv.x * wv.x + wv.y * wv.y + wv.z * wv.z + wv.w * wv.w;
        w[c] = wv;
    }
#pragma unroll
    for (int off = 16; off; off >>= 1)
        ss += __shfl_xor_sync(0xffffffffu, ss, off);

    __shared__ float red[8];
    __shared__ float s_scale;
    if ((tid & 31) == 0) red[tid >> 5] = ss;
    __syncthreads();
    if (tid == 0) {
        float t = 0.f;
#pragma unroll
        for (int i = 0; i < 8; i++) t += red[i];
        s_scale = mvec[row] / (sqrtf(t) + 1e-8f);
    }
    __syncthreads();
    const float sc = s_scale;
#pragma unroll
    for (int c = 0; c < 4; c++) {
        float vv[4] = {w[c].x * sc, w[c].y * sc, w[c].z * sc, w[c].w * sc};
        size_t base = (size_t)row * HID + (tid + 256 * c) * 4;
#pragma unroll
        for (int e = 0; e < 4; e++) {
            __nv_bfloat16 h = __float2bfloat16(vv[e]);
            Whi[base + e] = h;
            Wlo[base + e] = __float2bfloat16(vv[e] - __bfloat162float(h));
        }
    }
}

// ---------------- fp32 -> bf16 hi/lo split (x only) ----------------
__global__ __launch_bounds__(256) void split_bf16(
    const float* __restrict__ in, __nv_bfloat16* __restrict__ hi,
    __nv_bfloat16* __restrict__ lo, int n4)
{
    int i = blockIdx.x * 256 + threadIdx.x;
    if (i >= n4) return;
    float4 v = ((const float4*)in)[i];
    float vv[4] = {v.x, v.y, v.z, v.w};
    size_t base = (size_t)i * 4;
#pragma unroll
    for (int e = 0; e < 4; e++) {
        __nv_bfloat16 h = __float2bfloat16(vv[e]);
        hi[base + e] = h;
        lo[base + e] = __float2bfloat16(vv[e] - __bfloat162float(h));
    }
}

// ---------------- HMMA GEMM: C[M,N] = A[M,K]*B[N,K]^T, bf16 3-term split ----
#define STRIDE_B 80
#define TILE_B   (128 * STRIDE_B)
#define STAGE_B  (4 * TILE_B)
#define GEMM_SMEM (2 * STAGE_B)

__global__ __launch_bounds__(256, 1) void gemm_hmma(
    const __nv_bfloat16* __restrict__ Ah, const __nv_bfloat16* __restrict__ Al,
    const __nv_bfloat16* __restrict__ Bh, const __nv_bfloat16* __restrict__ Bl,
    float* __restrict__ C, __nv_bfloat16* __restrict__ Chi,
    __nv_bfloat16* __restrict__ Clo, int N, int mode)
{
    extern __shared__ char dsm[];
    const uint32_t sb = smem_u32(dsm);
    const int tid = threadIdx.x, lane = tid & 31, wid = tid >> 5;
    const int wm = wid & 3, wn = wid >> 2;
    const int row0 = blockIdx.y << 7, col0 = blockIdx.x << 7;
    const int K = 4096;

    const __nv_bfloat16* g0 = Ah + (size_t)row0 * K;
    const __nv_bfloat16* g1 = Al + (size_t)row0 * K;
    const __nv_bfloat16* g2 = Bh + (size_t)col0 * K;
    const __nv_bfloat16* g3 = Bl + (size_t)col0 * K;

    const int ldr = tid >> 2;
    const int ldc = (tid & 3) * 16;

    const uint32_t a_off = (uint32_t)(wm * 32 + (lane & 15)) * STRIDE_B + ((lane >> 4) * 16);
    const uint32_t b_off = (uint32_t)(wn * 64 + (((lane >> 4) << 3) + (lane & 7))) * STRIDE_B
                           + (((lane >> 3) & 1) * 16);

    float acc[2][8][4] = {};

#define LOAD_STAGE(buf, k0) do { \
    uint32_t s0_ = sb + (buf) * STAGE_B; \
    const __nv_bfloat16* gg_[4] = {g0 + (k0), g1 + (k0), g2 + (k0), g3 + (k0)}; \
    _Pragma("unroll") \
    for (int t_ = 0; t_ < 4; t_++) { \
        uint32_t st_ = s0_ + t_ * TILE_B; \
        _Pragma("unroll") \
        for (int p_ = 0; p_ < 2; p_++) { \
            int r_ = ldr + p_ * 64; \
            cp16(st_ + (uint32_t)r_ * STRIDE_B + ldc, \
                 (const char*)(gg_[t_] + (size_t)r_ * K) + ldc); \
        } \
    } \
    CP_COMMIT(); \
} while (0)

    LOAD_STAGE(0, 0);
    for (int ch = 0; ch < 128; ch++) {
        if (ch + 1 < 128) {
            LOAD_STAGE((ch + 1) & 1, (ch + 1) * 32);
            asm volatile("cp.async.wait_group 1;\n" ::: "memory");
        } else {
            asm volatile("cp.async.wait_group 0;\n" ::: "memory");
        }
        __syncthreads();
        const uint32_t s0 = sb + (ch & 1) * STAGE_B;
        const uint32_t sAh = s0, sAl = s0 + TILE_B;
        const uint32_t sBh = s0 + 2 * TILE_B, sBl = s0 + 3 * TILE_B;
#pragma unroll
        for (int k16 = 0; k16 < 2; k16++) {
            const uint32_t kadd = k16 * 32;
            uint32_t ah[2][4], al[2][4], bb[4][4];
            LDSM4(ah[0], sAh + a_off + kadd);
            LDSM4(ah[1], sAh + a_off + 16 * STRIDE_B + kadd);
            LDSM4(al[0], sAl + a_off + kadd);
            LDSM4(al[1], sAl + a_off + 16 * STRIDE_B + kadd);
#pragma unroll
            for (int j = 0; j < 4; j++) LDSM4(bb[j], sBh + b_off + j * 16 * STRIDE_B + kadd);
#pragma unroll
            for (int i = 0; i < 2; i++)
#pragma unroll
                for (int f = 0; f < 8; f++)
                    MMA16816(acc[i][f], ah[i], bb[f >> 1][(f & 1) * 2], bb[f >> 1][(f & 1) * 2 + 1]);
#pragma unroll
            for (int i = 0; i < 2; i++)
#pragma unroll
                for (int f = 0; f < 8; f++)
                    MMA16816(acc[i][f], al[i], bb[f >> 1][(f & 1) * 2], bb[f >> 1][(f & 1) * 2 + 1]);
#pragma unroll
            for (int j = 0; j < 4; j++) LDSM4(bb[j], sBl + b_off + j * 16 * STRIDE_B + kadd);
#pragma unroll
            for (int i = 0; i < 2; i++)
#pragma unroll
                for (int f = 0; f < 8; f++)
                    MMA16816(acc[i][f], ah[i], bb[f >> 1][(f & 1) * 2], bb[f >> 1][(f & 1) * 2 + 1]);
        }
        __syncthreads();
    }
#undef LOAD_STAGE

    if (mode == 0) {
#pragma unroll
        for (int i = 0; i < 2; i++) {
            const int mrow = row0 + wm * 32 + i * 16 + (lane >> 2);
#pragma unroll
            for (int f = 0; f < 8; f++) {
                const int col = col0 + wn * 64 + f * 8 + (lane & 3) * 2;
                float2 lo2 = {acc[i][f][0], acc[i][f][1]};
                float2 hi2 = {acc[i][f][2], acc[i][f][3]};
                *(float2*)&C[(size_t)mrow * N + col] = lo2;
                *(float2*)&C[(size_t)(mrow + 8) * N + col] = hi2;
            }
        }
    } else {
#pragma unroll
        for (int i = 0; i < 2; i++) {
            const int mrow = row0 + wm * 32 + i * 16 + (lane >> 2);
#pragma unroll
            for (int f = 0; f < 8; f++) {
                const int col = col0 + wn * 64 + f * 8 + (lane & 3) * 2;
                uint32_t h01 = pack_bf16x2(acc[i][f][1], acc[i][f][0]);
                float2 hf0 = unpack_bf16x2(h01);
                uint32_t l01 = pack_bf16x2(acc[i][f][1] - hf0.y, acc[i][f][0] - hf0.x);
                uint32_t h23 = pack_bf16x2(acc[i][f][3], acc[i][f][2]);
                float2 hf1 = unpack_bf16x2(h23);
                uint32_t l23 = pack_bf16x2(acc[i][f][3] - hf1.y, acc[i][f][2] - hf1.x);
                *(uint32_t*)&Chi[(size_t)mrow * N + col] = h01;
                *(uint32_t*)&Clo[(size_t)mrow * N + col] = l01;
                *(uint32_t*)&Chi[(size_t)(mrow + 8) * N + col] = h23;
                *(uint32_t*)&Clo[(size_t)(mrow + 8) * N + col] = l23;
            }
        }
    }
}

// ---------------- HMMA causal flash attention ----------------
// CTA: 128 q-rows (8 warps x 16 rows), key tiles of 64, D=128.
#define FSTR 272                 /* bytes per 128-elem bf16 row (136 elems) */
#define KV_T 17408               /* 64*FSTR */
#define KV_STAGE (4 * KV_T)      /* 69632 */
#define FLASH_SMEM (2 * KV_STAGE)

__global__ __launch_bounds__(256, 1) void flash_hmma(
    const __nv_bfloat16* __restrict__ qh_g, const __nv_bfloat16* __restrict__ ql_g,
    const __nv_bfloat16* __restrict__ kh_g, const __nv_bfloat16* __restrict__ kl_g,
    const __nv_bfloat16* __restrict__ vh_g, const __nv_bfloat16* __restrict__ vl_g,
    __nv_bfloat16* __restrict__ oh_g, __nv_bfloat16* __restrict__ ol_g)
{
    extern __shared__ char dsm[];
    const uint32_t sb = smem_u32(dsm);
    const int tid = threadIdx.x, lane = tid & 31, w = tid >> 5;
    const int qt = (int)gridDim.x - 1 - (int)blockIdx.x;   // big tiles first
    const int h = blockIdx.y, b = blockIdx.z;
    const int kvh = h >> 2;
    const int gr = qt * 128;
    const int nkt = 2 * qt + 2;

    // ---- stage Q (hi/lo) into smem, build A-frags in registers
    {
        const __nv_bfloat16* srcs[2] = {qh_g, ql_g};
#pragma unroll
        for (int t = 0; t < 2; t++) {
            uint32_t sdst = sb + t * (128 * FSTR);
            const __nv_bfloat16* src = srcs[t] + ((size_t)(b * SEQ + gr)) * HID + h * 128;
#pragma unroll
            for (int i = 0; i < 8; i++) {
                int idx = tid + i * 256;
                int r = idx >> 4, c = idx & 15;
                cp16(sdst + (uint32_t)r * FSTR + c * 16,
                     (const char*)(src + (size_t)r * HID) + c * 16);
            }
        }
        CP_COMMIT();
        asm volatile("cp.async.wait_group 0;\n" ::: "memory");
        __syncthreads();
    }
    uint32_t qhf[8][4], qlf[8][4];
    {
        const uint32_t qoff = (uint32_t)(w * 16 + (lane & 15)) * FSTR + ((lane >> 4) * 16);
#pragma unroll
        for (int kf = 0; kf < 8; kf++) {
            LDSM4(qhf[kf], sb + qoff + kf * 32);
            LDSM4(qlf[kf], sb + 128 * FSTR + qoff + kf * 32);
        }
    }
    __syncthreads();

    float o[16][4];
#pragma unroll
    for (int i = 0; i < 16; i++) { o[i][0] = 0.f; o[i][1] = 0.f; o[i][2] = 0.f; o[i][3] = 0.f; }
    float m0 = -1e5f, m1 = -1e5f, l0 = 0.f, l1 = 0.f;

    const uint32_t koff = (uint32_t)(((lane >> 4) << 3) + (lane & 7)) * FSTR + (((lane >> 3) & 1) * 16);
    const uint32_t voff = (uint32_t)((((lane >> 3) & 1) << 3) + (lane & 7)) * FSTR + ((lane >> 4) * 16);

    const __nv_bfloat16* kh_p = kh_g + ((size_t)(b * SEQ)) * KVD + kvh * 128;
    const __nv_bfloat16* kl_p = kl_g + ((size_t)(b * SEQ)) * KVD + kvh * 128;
    const __nv_bfloat16* vh_p = vh_g + ((size_t)(b * SEQ)) * KVD + kvh * 128;
    const __nv_bfloat16* vl_p = vl_g + ((size_t)(b * SEQ)) * KVD + kvh * 128;

#define LOADKV(kt_, buf_) do { \
    uint32_t s0_ = sb + (buf_) * KV_STAGE; \
    const __nv_bfloat16* gs_[4] = { \
        kh_p + (size_t)(kt_) * 64 * KVD, kl_p + (size_t)(kt_) * 64 * KVD, \
        vh_p + (size_t)(kt_) * 64 * KVD, vl_p + (size_t)(kt_) * 64 * KVD}; \
    _Pragma("unroll") \
    for (int t_ = 0; t_ < 4; t_++) { \
        _Pragma("unroll") \
        for (int i_ = 0; i_ < 4; i_++) { \
            int idx_ = tid + i_ * 256; \
            int r_ = idx_ >> 4, c_ = idx_ & 15; \
            cp16(s0_ + t_ * KV_T + (uint32_t)r_ * FSTR + c_ * 16, \
                 (const char*)(gs_[t_] + (size_t)r_ * KVD) + c_ * 16); \
        } \
    } \
    CP_COMMIT(); \
} while (0)

    LOADKV(0, 0);
    const float Cs = 0.08838834764831845f * 1.4426950408889634f;  // scale*log2e

    for (int kt = 0; kt < nkt; kt++) {
        if (kt + 1 < nkt) {
            LOADKV(kt + 1, (kt + 1) & 1);
            asm volatile("cp.async.wait_group 1;\n" ::: "memory");
        } else {
            asm volatile("cp.async.wait_group 0;\n" ::: "memory");
        }
        __syncthreads();

        const uint32_t sKh = sb + (kt & 1) * KV_STAGE;
        const uint32_t sKl = sKh + KV_T, sVh = sKh + 2 * KV_T, sVl = sKh + 3 * KV_T;

        // ---- QK^T (3-term split)
        float s[8][4];
#pragma unroll
        for (int i = 0; i < 8; i++) { s[i][0] = 0.f; s[i][1] = 0.f; s[i][2] = 0.f; s[i][3] = 0.f; }
#pragma unroll
        for (int kf = 0; kf < 8; kf++) {
#pragma unroll
            for (int nb = 0; nb < 4; nb++) {
                uint32_t bh[4], bl[4];
                LDSM4(bh, sKh + koff + nb * (16 * FSTR) + kf * 32);
                MMA16816(s[2 * nb], qhf[kf], bh[0], bh[1]);
                MMA16816(s[2 * nb + 1], qhf[kf], bh[2], bh[3]);
                MMA16816(s[2 * nb], qlf[kf], bh[0], bh[1]);
                MMA16816(s[2 * nb + 1], qlf[kf], bh[2], bh[3]);
                LDSM4(bl, sKl + koff + nb * (16 * FSTR) + kf * 32);
                MMA16816(s[2 * nb], qhf[kf], bl[0], bl[1]);
                MMA16816(s[2 * nb + 1], qhf[kf], bl[2], bl[3]);
            }
        }
#pragma unroll
        for (int nf = 0; nf < 8; nf++) {
            s[nf][0] *= Cs; s[nf][1] *= Cs; s[nf][2] *= Cs; s[nf][3] *= Cs;
        }
        // ---- causal mask (only the two diagonal tiles)
        if (kt >= nkt - 2) {
            const int r0 = gr + w * 16 + (lane >> 2);
            const int c0 = kt * 64 + 2 * (lane & 3);
#pragma unroll
            for (int nf = 0; nf < 8; nf++) {
#pragma unroll
                for (int j = 0; j < 4; j++) {
                    int col = c0 + nf * 8 + (j & 1);
                    int row = r0 + (j >> 1) * 8;
                    if (col > row) s[nf][j] = -1e5f;
                }
            }
        }
        // ---- online softmax (FMA-pipe exp2)
        float mx0 = -1e30f, mx1 = -1e30f;
#pragma unroll
        for (int nf = 0; nf < 8; nf++) {
            mx0 = fmaxf(mx0, fmaxf(s[nf][0], s[nf][1]));
            mx1 = fmaxf(mx1, fmaxf(s[nf][2], s[nf][3]));
        }
        mx0 = fmaxf(mx0, __shfl_xor_sync(0xffffffffu, mx0, 1));
        mx0 = fmaxf(mx0, __shfl_xor_sync(0xffffffffu, mx0, 2));
        mx1 = fmaxf(mx1, __shfl_xor_sync(0xffffffffu, mx1, 1));
        mx1 = fmaxf(mx1, __shfl_xor_sync(0xffffffffu, mx1, 2));
        const float mn0 = fmaxf(m0, mx0), mn1 = fmaxf(m1, mx1);
        const float cr0 = exp2p(m0 - mn0), cr1 = exp2p(m1 - mn1);
        m0 = mn0; m1 = mn1;
        float rs0 = 0.f, rs1 = 0.f;
#pragma unroll
        for (int nf = 0; nf < 8; nf++) {
            float p0 = exp2p(s[nf][0] - mn0), p1 = exp2p(s[nf][1] - mn0);
            float p2 = exp2p(s[nf][2] - mn1), p3 = exp2p(s[nf][3] - mn1);
            s[nf][0] = p0; s[nf][1] = p1; s[nf][2] = p2; s[nf][3] = p3;
            rs0 += p0 + p1; rs1 += p2 + p3;
        }
        rs0 += __shfl_xor_sync(0xffffffffu, rs0, 1);
        rs0 += __shfl_xor_sync(0xffffffffu, rs0, 2);
        rs1 += __shfl_xor_sync(0xffffffffu, rs1, 1);
        rs1 += __shfl_xor_sync(0xffffffffu, rs1, 2);
        l0 = l0 * cr0 + rs0;
        l1 = l1 * cr1 + rs1;
#pragma unroll
        for (int nf = 0; nf < 16; nf++) {
            o[nf][0] *= cr0; o[nf][1] *= cr0; o[nf][2] *= cr1; o[nf][3] *= cr1;
        }
        // ---- P @ V (3-term split); P acc-frag -> A-frag conversion
#pragma unroll
        for (int kb = 0; kb < 4; kb++) {
            uint32_t ph[4], pl[4];
#pragma unroll
            for (int q2 = 0; q2 < 2; q2++) {
                const int nf = 2 * kb + q2;
                uint32_t h01 = pack_bf16x2(s[nf][1], s[nf][0]);
                float2 f01 = unpack_bf16x2(h01);
                uint32_t l01 = pack_bf16x2(s[nf][1] - f01.y, s[nf][0] - f01.x);
                uint32_t h23 = pack_bf16x2(s[nf][3], s[nf][2]);
                float2 f23 = unpack_bf16x2(h23);
                uint32_t l23 = pack_bf16x2(s[nf][3] - f23.y, s[nf][2] - f23.x);
                ph[2 * q2] = h01; ph[2 * q2 + 1] = h23;
                pl[2 * q2] = l01; pl[2 * q2 + 1] = l23;
            }
            // reorder: a0=(r,k0-7)frag(2kb), a1=(r+8)frag(2kb), a2=(r)frag(2kb+1), a3=(r+8)frag(2kb+1)
            // ph currently: [0]=frag2kb rows r, [1]=frag2kb rows r+8, [2]=frag2kb+1 r, [3]=frag2kb+1 r+8 — matches.
#pragma unroll
            for (int ng = 0; ng < 8; ng++) {
                uint32_t vh[4], vl[4];
                LDSM4T(vh, sVh + voff + kb * (16 * FSTR) + ng * 32);
                MMA16816(o[2 * ng], ph, vh[0], vh[1]);
                MMA16816(o[2 * ng + 1], ph, vh[2], vh[3]);
                MMA16816(o[2 * ng], pl, vh[0], vh[1]);
                MMA16816(o[2 * ng + 1], pl, vh[2], vh[3]);
                LDSM4T(vl, sVl + voff + kb * (16 * FSTR) + ng * 32);
                MMA16816(o[2 * ng], ph, vl[0], vl[1]);
                MMA16816(o[2 * ng + 1], ph, vl[2], vl[3]);
            }
        }
        __syncthreads();
    }
#undef LOADKV

    // ---- epilogue: O/l -> bf16 hi/lo, store [TOK][HID]
    const float inv0 = 1.f / l0, inv1 = 1.f / l1;
    const size_t row0_ = (size_t)(b * SEQ + gr + w * 16 + (lane >> 2));
    const int colb = h * 128 + 2 * (lane & 3);
#pragma unroll
    for (int nf = 0; nf < 16; nf++) {
        const int col = colb + nf * 8;
        float v0 = o[nf][0] * inv0, v1 = o[nf][1] * inv0;
        float v2 = o[nf][2] * inv1, v3 = o[nf][3] * inv1;
        uint32_t h01 = pack_bf16x2(v1, v0);
        float2 f01 = unpack_bf16x2(h01);
        uint32_t l01 = pack_bf16x2(v1 - f01.y, v0 - f01.x);
        uint32_t h23 = pack_bf16x2(v3, v2);
        float2 f23 = unpack_bf16x2(h23);
        uint32_t l23 = pack_bf16x2(v3 - f23.y, v2 - f23.x);
        *(uint32_t*)&oh_g[row0_ * HID + col] = h01;
        *(uint32_t*)&ol_g[row0_ * HID + col] = l01;
        *(uint32_t*)&oh_g[(row0_ + 8) * HID + col] = h23;
        *(uint32_t*)&ol_g[(row0_ + 8) * HID + col] = l23;
    }
}

// ---------------- launch ----------------
extern "C" void kernel_launch(void* const* d_in, const int* in_sizes, int n_in,
                              void* d_out, int out_size)
{
    const float* x  = (const float*)d_in[0];
    const float* Wq = (const float*)d_in[2];
    const float* Aq = (const float*)d_in[3];
    const float* Bq = (const float*)d_in[4];
    const float* mq = (const float*)d_in[5];
    const float* Wk = (const float*)d_in[6];
    const float* Ak = (const float*)d_in[7];
    const float* Bk = (const float*)d_in[8];
    const float* mk = (const float*)d_in[9];
    const float* Wv = (const float*)d_in[10];
    const float* Av = (const float*)d_in[11];
    const float* Bv = (const float*)d_in[12];
    const float* mv = (const float*)d_in[13];
    const float* Wo = (const float*)d_in[14];
    const float* Ao = (const float*)d_in[15];
    const float* Bo = (const float*)d_in[16];
    const float* mo = (const float*)d_in[17];

    __nv_bfloat16 *xh, *xl, *Wqh, *Wql, *Wkh, *Wkl, *Wvh, *Wvl, *Woh, *Wol;
    __nv_bfloat16 *qh, *ql, *kh, *kl, *vh, *vl, *ath, *atl;
    cudaGetSymbolAddress((void**)&xh, g_xh);   cudaGetSymbolAddress((void**)&xl, g_xl);
    cudaGetSymbolAddress((void**)&Wqh, g_Wqh); cudaGetSymbolAddress((void**)&Wql, g_Wql);
    cudaGetSymbolAddress((void**)&Wkh, g_Wkh); cudaGetSymbolAddress((void**)&Wkl, g_Wkl);
    cudaGetSymbolAddress((void**)&Wvh, g_Wvh); cudaGetSymbolAddress((void**)&Wvl, g_Wvl);
    cudaGetSymbolAddress((void**)&Woh, g_Woh); cudaGetSymbolAddress((void**)&Wol, g_Wol);
    cudaGetSymbolAddress((void**)&qh, g_qh);   cudaGetSymbolAddress((void**)&ql, g_ql);
    cudaGetSymbolAddress((void**)&kh, g_kh);   cudaGetSymbolAddress((void**)&kl, g_kl);
    cudaGetSymbolAddress((void**)&vh, g_vh);   cudaGetSymbolAddress((void**)&vl, g_vl);
    cudaGetSymbolAddress((void**)&ath, g_ath); cudaGetSymbolAddress((void**)&atl, g_atl);

    cudaFuncSetAttribute(gemm_hmma, cudaFuncAttributeMaxDynamicSharedMemorySize, GEMM_SMEM);
    cudaFuncSetAttribute(flash_hmma, cudaFuncAttributeMaxDynamicSharedMemorySize, FLASH_SMEM);

    // 1) DoRA effective weights (bf16 hi/lo)
    dora_weights<<<HID, 256>>>(Wq, Aq, Bq, mq, Wqh, Wql);
    dora_weights<<<KVD, 256>>>(Wk, Ak, Bk, mk, Wkh, Wkl);
    dora_weights<<<KVD, 256>>>(Wv, Av, Bv, mv, Wvh, Wvl);
    dora_weights<<<HID, 256>>>(Wo, Ao, Bo, mo, Woh, Wol);

    // 2) split x
    split_bf16<<<(TOK * HID / 4 + 255) / 256, 256>>>(x, xh, xl, TOK * HID / 4);

    // 3) q/k/v projections -> bf16 hi/lo directly
    gemm_hmma<<<dim3(HID / 128, TOK / 128), 256, GEMM_SMEM>>>(xh, xl, Wqh, Wql, nullptr, qh, ql, HID, 1);
    gemm_hmma<<<dim3(KVD / 128, TOK / 128), 256, GEMM_SMEM>>>(xh, xl, Wkh, Wkl, nullptr, kh, kl, KVD, 1);
    gemm_hmma<<<dim3(KVD / 128, TOK / 128), 256, GEMM_SMEM>>>(xh, xl, Wvh, Wvl, nullptr, vh, vl, KVD, 1);

    // 4) causal attention (HMMA) -> bf16 hi/lo attention output
    flash_hmma<<<dim3(SEQ / 128, 32, 2), 256, FLASH_SMEM>>>(qh, ql, kh, kl, vh, vl, ath, atl);

    // 5) output projection -> d_out (fp32)
    gemm_hmma<<<dim3(HID / 128, TOK / 128), 256, GEMM_SMEM>>>(ath, atl, Woh, Wol, (float*)d_out, nullptr, nullptr, HID, 0);
}